// round 2
// baseline (speedup 1.0000x reference)
#include <cuda_runtime.h>
#include <math_constants.h>

#define N_NODES 50000
#define N_EDGES 800000
#define ET (N_EDGES + N_NODES)   // + self loops
#define C 64
#define F_IN 128
#define NEG_SLOPE 0.2f

// ---------------- scratch (static device globals; no allocation) ----------------
__device__ int      g_src[ET];
__device__ int      g_dst[ET];
__device__ float    g_h[(size_t)N_NODES * C];     // per-layer transformed features
__device__ float    g_out0[(size_t)N_NODES * C];  // layer-0 output
__device__ float    g_out1[(size_t)N_NODES * C];  // layer-1 output
__device__ float    g_ssrc[N_NODES];
__device__ float    g_sdst[N_NODES];
__device__ unsigned g_m[N_NODES];                 // encoded float max
__device__ float    g_den[N_NODES];
__device__ float    g_e[ET];                      // edge score, then exp(e-m)

// ordered-uint encoding for float atomicMax (handles negatives)
__device__ __forceinline__ unsigned fenc(float f) {
    unsigned u = __float_as_uint(f);
    return (u & 0x80000000u) ? ~u : (u | 0x80000000u);
}
__device__ __forceinline__ float fdec(unsigned e) {
    unsigned u = (e & 0x80000000u) ? (e ^ 0x80000000u) : ~e;
    return __uint_as_float(u);
}

// ---------------- kernels ----------------

__global__ void prep_edges(const int* __restrict__ ei) {
    int i = blockIdx.x * blockDim.x + threadIdx.x;
    if (i >= ET) return;
    if (i < N_EDGES) {
        g_src[i] = ei[i];
        g_dst[i] = ei[N_EDGES + i];
    } else {
        int n = i - N_EDGES;
        g_src[i] = n;
        g_dst[i] = n;
    }
}

__global__ void init_md() {
    int i = blockIdx.x * blockDim.x + threadIdx.x;
    if (i >= N_NODES) return;
    g_m[i] = fenc(-CUDART_INF_F);
    g_den[i] = 0.0f;
}

template <bool SECOND>
__global__ void init_out(const float* __restrict__ b) {
    int i = blockIdx.x * blockDim.x + threadIdx.x;
    if (i >= N_NODES * C) return;
    float* out = SECOND ? g_out1 : g_out0;
    out[i] = b[i & (C - 1)];
}

// h = X @ W  (X: [N,K], W: [K,64]); also s_src = h.att_src, s_dst = h.att_dst
// block: (64, 4) -> 4 nodes per block
template <int K, bool X_FROM_OUT0>
__global__ void gemm_att(const float* __restrict__ Xext,
                         const float* __restrict__ W,
                         const float* __restrict__ att_src,
                         const float* __restrict__ att_dst) {
    const int NPB = 4;
    __shared__ float xs[NPB][K];
    __shared__ float r1[NPB][2];
    __shared__ float r2[NPB][2];

    const float* X = X_FROM_OUT0 ? g_out0 : Xext;
    int y = threadIdx.y;
    int c = threadIdx.x;                 // 0..63
    int node = blockIdx.x * NPB + y;     // N divisible by 4

    for (int k = c; k < K; k += 64)
        xs[y][k] = X[(size_t)node * K + k];
    __syncthreads();

    float acc = 0.0f;
#pragma unroll 8
    for (int k = 0; k < K; k++)
        acc = fmaf(xs[y][k], W[k * C + c], acc);

    g_h[(size_t)node * C + c] = acc;

    float p1 = acc * att_src[c];
    float p2 = acc * att_dst[c];
#pragma unroll
    for (int o = 16; o > 0; o >>= 1) {
        p1 += __shfl_down_sync(0xffffffffu, p1, o);
        p2 += __shfl_down_sync(0xffffffffu, p2, o);
    }
    int half = c >> 5;
    if ((c & 31) == 0) { r1[y][half] = p1; r2[y][half] = p2; }
    __syncthreads();
    if (c == 0) {
        g_ssrc[node] = r1[y][0] + r1[y][1];
        g_sdst[node] = r2[y][0] + r2[y][1];
    }
}

__global__ void edge_score() {
    int i = blockIdx.x * blockDim.x + threadIdx.x;
    if (i >= ET) return;
    int s = g_src[i], d = g_dst[i];
    float e = g_ssrc[s] + g_sdst[d];
    e = (e > 0.0f) ? e : NEG_SLOPE * e;   // leaky relu
    g_e[i] = e;
    atomicMax(&g_m[d], fenc(e));
}

__global__ void edge_exp() {
    int i = blockIdx.x * blockDim.x + threadIdx.x;
    if (i >= ET) return;
    int d = g_dst[i];
    float ex = __expf(g_e[i] - fdec(g_m[d]));
    g_e[i] = ex;
    atomicAdd(&g_den[d], ex);
}

// warp per edge; 64 channels -> 2 atomics per lane
template <bool SECOND>
__global__ void edge_scatter() {
    int gt = blockIdx.x * blockDim.x + threadIdx.x;
    int edge = gt >> 5;
    int lane = gt & 31;
    if (edge >= ET) return;
    int s = g_src[edge], d = g_dst[edge];
    float w = g_e[edge] / g_den[d];
    const float* hr = &g_h[(size_t)s * C];
    float* orow = (SECOND ? g_out1 : g_out0) + (size_t)d * C;
    atomicAdd(&orow[lane],      w * hr[lane]);
    atomicAdd(&orow[lane + 32], w * hr[lane + 32]);
}

// relu(relu(y @ W0 + b0) @ W1 + b1); block = 64 threads = 1 node
__global__ void mlp_head(const float* __restrict__ W0, const float* __restrict__ b0,
                         const float* __restrict__ W1, const float* __restrict__ b1,
                         float* __restrict__ out) {
    __shared__ float ys[C];
    __shared__ float ts[C];
    int node = blockIdx.x;
    int c = threadIdx.x;
    ys[c] = g_out1[(size_t)node * C + c];
    __syncthreads();
    float acc = b0[c];
#pragma unroll
    for (int k = 0; k < C; k++)
        acc = fmaf(ys[k], W0[k * C + c], acc);
    ts[c] = fmaxf(acc, 0.0f);
    __syncthreads();
    if (c < 10) {
        float a = b1[c];
#pragma unroll
        for (int k = 0; k < C; k++)
            a = fmaf(ts[k], W1[k * 10 + c], a);
        out[node * 10 + c] = fmaxf(a, 0.0f);
    }
}

// ---------------- launch ----------------

extern "C" void kernel_launch(void* const* d_in, const int* in_sizes, int n_in,
                              void* d_out, int out_size) {
    const float* x       = (const float*)d_in[0];
    const int*   ei      = (const int*)d_in[1];
    const float* g0_W    = (const float*)d_in[2];
    const float* g0_as   = (const float*)d_in[3];
    const float* g0_ad   = (const float*)d_in[4];
    const float* g0_b    = (const float*)d_in[5];
    const float* g1_W    = (const float*)d_in[6];
    const float* g1_as   = (const float*)d_in[7];
    const float* g1_ad   = (const float*)d_in[8];
    const float* g1_b    = (const float*)d_in[9];
    const float* l0_W    = (const float*)d_in[10];
    const float* l0_b    = (const float*)d_in[11];
    const float* l1_W    = (const float*)d_in[12];
    const float* l1_b    = (const float*)d_in[13];
    float* out = (float*)d_out;

    const int TB = 256;
    const int eb = (ET + TB - 1) / TB;            // per-edge grids
    const int nb = (N_NODES + TB - 1) / TB;
    const int ob = (N_NODES * C) / TB;            // 12500
    const int sb = (ET * 32 + TB - 1) / TB;       // warp-per-edge scatter
    dim3 gblk(64, 4);
    const int gb = N_NODES / 4;

    prep_edges<<<eb, TB>>>(ei);

    // ---- GAT layer 0: x(128) -> out0(64) ----
    init_md<<<nb, TB>>>();
    init_out<false><<<ob, TB>>>(g0_b);
    gemm_att<F_IN, false><<<gb, gblk>>>(x, g0_W, g0_as, g0_ad);
    edge_score<<<eb, TB>>>();
    edge_exp<<<eb, TB>>>();
    edge_scatter<false><<<sb, TB>>>();

    // ---- GAT layer 1: out0(64) -> out1(64) ----
    init_md<<<nb, TB>>>();
    init_out<true><<<ob, TB>>>(g1_b);
    gemm_att<C, true><<<gb, gblk>>>(nullptr, g1_W, g1_as, g1_ad);
    edge_score<<<eb, TB>>>();
    edge_exp<<<eb, TB>>>();
    edge_scatter<true><<<sb, TB>>>();

    // ---- MLP head ----
    mlp_head<<<N_NODES, 64>>>(l0_W, l0_b, l1_W, l1_b, out);
}

// round 3
// speedup vs baseline: 1.7824x; 1.7824x over previous
#include <cuda_runtime.h>
#include <math_constants.h>

#define N_NODES 50000
#define N_EDGES 800000
#define ET (N_EDGES + N_NODES)   // + self loops
#define C 64
#define F_IN 128
#define NEG_SLOPE 0.2f

#define BS_SCAN 512
#define NSCAN_BLOCKS ((N_NODES + BS_SCAN - 1) / BS_SCAN)   // 98

// ---------------- scratch (static device globals; no allocation) ----------------
__device__ int   g_src[ET];
__device__ int   g_dst[ET];
__device__ int   g_cnt[N_NODES];
__device__ int   g_fill[N_NODES];
__device__ int   g_rowoff[N_NODES + 1];
__device__ int   g_bsum[NSCAN_BLOCKS];
__device__ int   g_csrc[ET];                     // CSR: src sorted by dst
__device__ float g_h[(size_t)N_NODES * C];
__device__ float g_out0[(size_t)N_NODES * C];
__device__ float g_out1[(size_t)N_NODES * C];
__device__ float g_ssrc[N_NODES];
__device__ float g_sdst[N_NODES];

// ---------------- CSR build ----------------

__global__ void zero_counts() {
    int i = blockIdx.x * blockDim.x + threadIdx.x;
    if (i < N_NODES) { g_cnt[i] = 0; g_fill[i] = 0; }
}

__global__ void prep_hist(const int* __restrict__ ei) {
    int i = blockIdx.x * blockDim.x + threadIdx.x;
    if (i >= ET) return;
    int s, d;
    if (i < N_EDGES) { s = ei[i]; d = ei[N_EDGES + i]; }
    else             { s = i - N_EDGES; d = s; }
    g_src[i] = s;
    g_dst[i] = d;
    atomicAdd(&g_cnt[d], 1);
}

__global__ void scan_block() {
    __shared__ int s[BS_SCAN];
    int t = threadIdx.x;
    int i = blockIdx.x * BS_SCAN + t;
    int v = (i < N_NODES) ? g_cnt[i] : 0;
    s[t] = v;
    __syncthreads();
#pragma unroll
    for (int off = 1; off < BS_SCAN; off <<= 1) {
        int add = (t >= off) ? s[t - off] : 0;
        __syncthreads();
        s[t] += add;
        __syncthreads();
    }
    if (i < N_NODES) g_rowoff[i + 1] = s[t];
    if (t == BS_SCAN - 1) g_bsum[blockIdx.x] = s[t];
}

__global__ void scan_top() {
    if (threadIdx.x == 0) {
        int run = 0;
        for (int b = 0; b < NSCAN_BLOCKS; b++) {
            int t = g_bsum[b];
            g_bsum[b] = run;
            run += t;
        }
    }
}

__global__ void scan_add() {
    int i = blockIdx.x * blockDim.x + threadIdx.x;
    if (i < N_NODES) g_rowoff[i + 1] += g_bsum[i / BS_SCAN];
    if (i == 0) g_rowoff[0] = 0;
}

__global__ void csr_fill() {
    int i = blockIdx.x * blockDim.x + threadIdx.x;
    if (i >= ET) return;
    int d = g_dst[i];
    int pos = g_rowoff[d] + atomicAdd(&g_fill[d], 1);
    g_csrc[pos] = g_src[i];
}

// ---------------- fused GEMM + attention dots ----------------
// h = X @ W  (X: [N,K], W: [K,64]); s_src = h.att_src; s_dst = h.att_dst
// block: 256 threads = 16x16, tile 64 nodes x 64 channels, 4x4 per thread.
template <int K, bool X_FROM_OUT0>
__global__ void gemm_att2(const float* __restrict__ Xext,
                          const float* __restrict__ W,
                          const float* __restrict__ av_s,
                          const float* __restrict__ av_d) {
    extern __shared__ float sm[];
    float (*Xs)[K + 1] = (float (*)[K + 1])sm;            // 64 x (K+1)
    float* Bsm = sm + 64 * (K + 1);                        // K x 64

    const float* X = X_FROM_OUT0 ? g_out0 : Xext;
    int tid = threadIdx.x;
    int tx = tid & 15;                 // channel group -> channels tx*4..tx*4+3
    int ty = tid >> 4;                 // node group    -> nodes ty*4..ty*4+3
    int nodeBase = blockIdx.x * 64;

    for (int idx = tid; idx < 64 * K; idx += 256) {
        int r = idx / K, k = idx - r * K;
        int n = nodeBase + r;
        Xs[r][k] = (n < N_NODES) ? X[(size_t)n * K + k] : 0.0f;
    }
    for (int idx = tid; idx < K * C; idx += 256)
        Bsm[idx] = W[idx];
    __syncthreads();

    float acc[4][4] = {};
#pragma unroll 2
    for (int k = 0; k < K; k++) {
        float4 b = *(const float4*)&Bsm[k * C + tx * 4];
        float a0 = Xs[ty * 4 + 0][k];
        float a1 = Xs[ty * 4 + 1][k];
        float a2 = Xs[ty * 4 + 2][k];
        float a3 = Xs[ty * 4 + 3][k];
        acc[0][0] = fmaf(a0, b.x, acc[0][0]); acc[0][1] = fmaf(a0, b.y, acc[0][1]);
        acc[0][2] = fmaf(a0, b.z, acc[0][2]); acc[0][3] = fmaf(a0, b.w, acc[0][3]);
        acc[1][0] = fmaf(a1, b.x, acc[1][0]); acc[1][1] = fmaf(a1, b.y, acc[1][1]);
        acc[1][2] = fmaf(a1, b.z, acc[1][2]); acc[1][3] = fmaf(a1, b.w, acc[1][3]);
        acc[2][0] = fmaf(a2, b.x, acc[2][0]); acc[2][1] = fmaf(a2, b.y, acc[2][1]);
        acc[2][2] = fmaf(a2, b.z, acc[2][2]); acc[2][3] = fmaf(a2, b.w, acc[2][3]);
        acc[3][0] = fmaf(a3, b.x, acc[3][0]); acc[3][1] = fmaf(a3, b.y, acc[3][1]);
        acc[3][2] = fmaf(a3, b.z, acc[3][2]); acc[3][3] = fmaf(a3, b.w, acc[3][3]);
    }
    __syncthreads();

    // reuse Xs area as Hs[64][C+1]
    float (*Hs)[C + 1] = (float (*)[C + 1])sm;
#pragma unroll
    for (int mi = 0; mi < 4; mi++) {
        int r = ty * 4 + mi;
        int n = nodeBase + r;
        if (n < N_NODES) {
            float4 v = make_float4(acc[mi][0], acc[mi][1], acc[mi][2], acc[mi][3]);
            *(float4*)&g_h[(size_t)n * C + tx * 4] = v;
        }
        Hs[r][tx * 4 + 0] = acc[mi][0];
        Hs[r][tx * 4 + 1] = acc[mi][1];
        Hs[r][tx * 4 + 2] = acc[mi][2];
        Hs[r][tx * 4 + 3] = acc[mi][3];
    }
    __syncthreads();

    // attention dots: 8 warps, each handles 8 node rows
    int w = tid >> 5, lane = tid & 31;
    float as0 = av_s[lane], as1 = av_s[lane + 32];
    float ad0 = av_d[lane], ad1 = av_d[lane + 32];
    for (int r = w; r < 64; r += 8) {
        float h0 = Hs[r][lane], h1 = Hs[r][lane + 32];
        float p1 = h0 * as0 + h1 * as1;
        float p2 = h0 * ad0 + h1 * ad1;
#pragma unroll
        for (int o = 16; o > 0; o >>= 1) {
            p1 += __shfl_down_sync(0xffffffffu, p1, o);
            p2 += __shfl_down_sync(0xffffffffu, p2, o);
        }
        int n = nodeBase + r;
        if (lane == 0 && n < N_NODES) { g_ssrc[n] = p1; g_sdst[n] = p2; }
    }
}

// ---------------- CSR pull aggregation with online softmax ----------------
// warp per destination node; lanes hold 2 channels each
template <bool SECOND>
__global__ void aggregate(const float* __restrict__ bias) {
    int gt = blockIdx.x * blockDim.x + threadIdx.x;
    int d = gt >> 5;
    int lane = gt & 31;
    if (d >= N_NODES) return;
    int beg = g_rowoff[d], end = g_rowoff[d + 1];
    float sd = g_sdst[d];

    float m = -CUDART_INF_F, den = 0.0f, a0 = 0.0f, a1 = 0.0f;
    int s_next = g_csrc[beg];
    float ss_next = g_ssrc[s_next];
    for (int j = beg; j < end; j++) {
        int s = s_next;
        float ss = ss_next;
        if (j + 1 < end) {                 // software prefetch of next edge
            s_next = g_csrc[j + 1];
            ss_next = g_ssrc[s_next];
        }
        float e = ss + sd;
        e = (e > 0.0f) ? e : NEG_SLOPE * e;
        float mn = fmaxf(m, e);
        float sc = __expf(m - mn);         // 0 on first iter (m=-inf), else <=1
        float wgt = __expf(e - mn);
        float h0 = g_h[(size_t)s * C + lane];
        float h1 = g_h[(size_t)s * C + lane + 32];
        den = den * sc + wgt;
        a0 = fmaf(a0, sc, wgt * h0);
        a1 = fmaf(a1, sc, wgt * h1);
        m = mn;
    }
    float inv = 1.0f / den;
    float* o = (SECOND ? g_out1 : g_out0) + (size_t)d * C;
    o[lane]      = a0 * inv + bias[lane];
    o[lane + 32] = a1 * inv + bias[lane + 32];
}

// ---------------- MLP head ----------------
__global__ void mlp_head(const float* __restrict__ W0, const float* __restrict__ b0,
                         const float* __restrict__ W1, const float* __restrict__ b1,
                         float* __restrict__ out) {
    __shared__ float ys[C];
    __shared__ float ts[C];
    int node = blockIdx.x;
    int c = threadIdx.x;
    ys[c] = g_out1[(size_t)node * C + c];
    __syncthreads();
    float acc = b0[c];
#pragma unroll
    for (int k = 0; k < C; k++)
        acc = fmaf(ys[k], W0[k * C + c], acc);
    ts[c] = fmaxf(acc, 0.0f);
    __syncthreads();
    if (c < 10) {
        float a = b1[c];
#pragma unroll
        for (int k = 0; k < C; k++)
            a = fmaf(ts[k], W1[k * 10 + c], a);
        out[node * 10 + c] = fmaxf(a, 0.0f);
    }
}

// ---------------- launch ----------------

extern "C" void kernel_launch(void* const* d_in, const int* in_sizes, int n_in,
                              void* d_out, int out_size) {
    const float* x     = (const float*)d_in[0];
    const int*   ei    = (const int*)d_in[1];
    const float* g0_W  = (const float*)d_in[2];
    const float* g0_as = (const float*)d_in[3];
    const float* g0_ad = (const float*)d_in[4];
    const float* g0_b  = (const float*)d_in[5];
    const float* g1_W  = (const float*)d_in[6];
    const float* g1_as = (const float*)d_in[7];
    const float* g1_ad = (const float*)d_in[8];
    const float* g1_b  = (const float*)d_in[9];
    const float* l0_W  = (const float*)d_in[10];
    const float* l0_b  = (const float*)d_in[11];
    const float* l1_W  = (const float*)d_in[12];
    const float* l1_b  = (const float*)d_in[13];
    float* out = (float*)d_out;

    const int TB = 256;
    const int eb = (ET + TB - 1) / TB;
    const int nb = (N_NODES + TB - 1) / TB;
    const int ab = (N_NODES * 32 + TB - 1) / TB;     // warp per node
    const int gb = (N_NODES + 63) / 64;              // 782

    const int smem0 = (64 * (F_IN + 1) + F_IN * C) * (int)sizeof(float);  // ~65.8 KB
    const int smem1 = (64 * (C + 1) + C * C) * (int)sizeof(float);        // ~33 KB
    cudaFuncSetAttribute(gemm_att2<F_IN, false>,
                         cudaFuncAttributeMaxDynamicSharedMemorySize, smem0);

    // CSR build (once; shared by both layers)
    zero_counts<<<nb, TB>>>();
    prep_hist<<<eb, TB>>>(ei);
    scan_block<<<NSCAN_BLOCKS, BS_SCAN>>>();
    scan_top<<<1, 32>>>();
    scan_add<<<nb, TB>>>();
    csr_fill<<<eb, TB>>>();

    // ---- GAT layer 0 ----
    gemm_att2<F_IN, false><<<gb, 256, smem0>>>(x, g0_W, g0_as, g0_ad);
    aggregate<false><<<ab, TB>>>(g0_b);

    // ---- GAT layer 1 ----
    gemm_att2<C, true><<<gb, 256, smem1>>>(nullptr, g1_W, g1_as, g1_ad);
    aggregate<true><<<ab, TB>>>(g1_b);

    // ---- MLP head ----
    mlp_head<<<N_NODES, 64>>>(l0_W, l0_b, l1_W, l1_b, out);
}

// round 4
// speedup vs baseline: 1.9564x; 1.0976x over previous
#include <cuda_runtime.h>
#include <math_constants.h>

#define N_NODES 50000
#define N_EDGES 800000
#define ET (N_EDGES + N_NODES)   // + self loops
#define C 64
#define F_IN 128
#define NEG_SLOPE 0.2f
#define NEG_BIG (-1e30f)

#define BS_SCAN 512
#define NSCAN_BLOCKS ((N_NODES + BS_SCAN - 1) / BS_SCAN)   // 98

// ---------------- scratch (static device globals; no allocation) ----------------
__device__ int   g_src[ET];
__device__ int   g_dst[ET];
__device__ int   g_cnt[N_NODES];
__device__ int   g_fill[N_NODES];
__device__ int   g_rowoff[N_NODES + 1];
__device__ int   g_bsum[NSCAN_BLOCKS];
__device__ int   g_csrc[ET];                     // CSR: src sorted by dst
__device__ float g_h[(size_t)N_NODES * C];
__device__ float g_out0[(size_t)N_NODES * C];
__device__ float g_out1[(size_t)N_NODES * C];
__device__ float g_ssrc[N_NODES];
__device__ float g_sdst[N_NODES];

// ---------------- CSR build ----------------

__global__ void zero_counts() {
    int i = blockIdx.x * blockDim.x + threadIdx.x;
    if (i < N_NODES) { g_cnt[i] = 0; g_fill[i] = 0; }
}

__global__ void prep_hist(const int* __restrict__ ei) {
    int i = blockIdx.x * blockDim.x + threadIdx.x;
    if (i >= ET) return;
    int s, d;
    if (i < N_EDGES) { s = ei[i]; d = ei[N_EDGES + i]; }
    else             { s = i - N_EDGES; d = s; }
    g_src[i] = s;
    g_dst[i] = d;
    atomicAdd(&g_cnt[d], 1);
}

__global__ void scan_block() {
    __shared__ int s[BS_SCAN];
    int t = threadIdx.x;
    int i = blockIdx.x * BS_SCAN + t;
    int v = (i < N_NODES) ? g_cnt[i] : 0;
    s[t] = v;
    __syncthreads();
#pragma unroll
    for (int off = 1; off < BS_SCAN; off <<= 1) {
        int add = (t >= off) ? s[t - off] : 0;
        __syncthreads();
        s[t] += add;
        __syncthreads();
    }
    if (i < N_NODES) g_rowoff[i + 1] = s[t];
    if (t == BS_SCAN - 1) g_bsum[blockIdx.x] = s[t];
}

// parallel exclusive scan over the 98 block sums (128 threads)
__global__ void scan_top() {
    int t = threadIdx.x;
    int lane = t & 31, w = t >> 5;
    int v = (t < NSCAN_BLOCKS) ? g_bsum[t] : 0;
    int x = v;
#pragma unroll
    for (int o = 1; o < 32; o <<= 1) {
        int y = __shfl_up_sync(0xffffffffu, x, o);
        if (lane >= o) x += y;
    }
    __shared__ int wsum[4];
    if (lane == 31) wsum[w] = x;
    __syncthreads();
    int add = 0;
#pragma unroll
    for (int i = 0; i < 4; i++)
        if (i < w) add += wsum[i];
    if (t < NSCAN_BLOCKS) g_bsum[t] = x + add - v;   // exclusive
}

__global__ void scan_add() {
    int i = blockIdx.x * blockDim.x + threadIdx.x;
    if (i < N_NODES) g_rowoff[i + 1] += g_bsum[i / BS_SCAN];
    if (i == 0) g_rowoff[0] = 0;
}

__global__ void csr_fill() {
    int i = blockIdx.x * blockDim.x + threadIdx.x;
    if (i >= ET) return;
    int d = g_dst[i];
    int pos = g_rowoff[d] + atomicAdd(&g_fill[d], 1);
    g_csrc[pos] = g_src[i];
}

// ---------------- fused GEMM + attention dots ----------------
// h = X @ W  (X: [N,K], W: [K,64]); s_src = h.att_src; s_dst = h.att_dst
// block: 256 threads = 16x16, tile 64 nodes x 64 channels, 4x4 per thread.
template <int K, bool X_FROM_OUT0>
__global__ void gemm_att2(const float* __restrict__ Xext,
                          const float* __restrict__ W,
                          const float* __restrict__ av_s,
                          const float* __restrict__ av_d) {
    extern __shared__ float sm[];
    float (*Xs)[K + 1] = (float (*)[K + 1])sm;            // 64 x (K+1)
    float* Bsm = sm + 64 * (K + 1);                        // K x 64

    const float* X = X_FROM_OUT0 ? g_out0 : Xext;
    int tid = threadIdx.x;
    int tx = tid & 15;
    int ty = tid >> 4;
    int nodeBase = blockIdx.x * 64;

    for (int idx = tid; idx < 64 * K; idx += 256) {
        int r = idx / K, k = idx - r * K;
        int n = nodeBase + r;
        Xs[r][k] = (n < N_NODES) ? X[(size_t)n * K + k] : 0.0f;
    }
    for (int idx = tid; idx < K * C; idx += 256)
        Bsm[idx] = W[idx];
    __syncthreads();

    float acc[4][4] = {};
#pragma unroll 2
    for (int k = 0; k < K; k++) {
        float4 b = *(const float4*)&Bsm[k * C + tx * 4];
        float a0 = Xs[ty * 4 + 0][k];
        float a1 = Xs[ty * 4 + 1][k];
        float a2 = Xs[ty * 4 + 2][k];
        float a3 = Xs[ty * 4 + 3][k];
        acc[0][0] = fmaf(a0, b.x, acc[0][0]); acc[0][1] = fmaf(a0, b.y, acc[0][1]);
        acc[0][2] = fmaf(a0, b.z, acc[0][2]); acc[0][3] = fmaf(a0, b.w, acc[0][3]);
        acc[1][0] = fmaf(a1, b.x, acc[1][0]); acc[1][1] = fmaf(a1, b.y, acc[1][1]);
        acc[1][2] = fmaf(a1, b.z, acc[1][2]); acc[1][3] = fmaf(a1, b.w, acc[1][3]);
        acc[2][0] = fmaf(a2, b.x, acc[2][0]); acc[2][1] = fmaf(a2, b.y, acc[2][1]);
        acc[2][2] = fmaf(a2, b.z, acc[2][2]); acc[2][3] = fmaf(a2, b.w, acc[2][3]);
        acc[3][0] = fmaf(a3, b.x, acc[3][0]); acc[3][1] = fmaf(a3, b.y, acc[3][1]);
        acc[3][2] = fmaf(a3, b.z, acc[3][2]); acc[3][3] = fmaf(a3, b.w, acc[3][3]);
    }
    __syncthreads();

    float (*Hs)[C + 1] = (float (*)[C + 1])sm;
#pragma unroll
    for (int mi = 0; mi < 4; mi++) {
        int r = ty * 4 + mi;
        int n = nodeBase + r;
        if (n < N_NODES) {
            float4 v = make_float4(acc[mi][0], acc[mi][1], acc[mi][2], acc[mi][3]);
            *(float4*)&g_h[(size_t)n * C + tx * 4] = v;
        }
        Hs[r][tx * 4 + 0] = acc[mi][0];
        Hs[r][tx * 4 + 1] = acc[mi][1];
        Hs[r][tx * 4 + 2] = acc[mi][2];
        Hs[r][tx * 4 + 3] = acc[mi][3];
    }
    __syncthreads();

    int w = tid >> 5, lane = tid & 31;
    float as0 = av_s[lane], as1 = av_s[lane + 32];
    float ad0 = av_d[lane], ad1 = av_d[lane + 32];
    for (int r = w; r < 64; r += 8) {
        float h0 = Hs[r][lane], h1 = Hs[r][lane + 32];
        float p1 = h0 * as0 + h1 * as1;
        float p2 = h0 * ad0 + h1 * ad1;
#pragma unroll
        for (int o = 16; o > 0; o >>= 1) {
            p1 += __shfl_down_sync(0xffffffffu, p1, o);
            p2 += __shfl_down_sync(0xffffffffu, p2, o);
        }
        int n = nodeBase + r;
        if (lane == 0 && n < N_NODES) { g_ssrc[n] = p1; g_sdst[n] = p2; }
    }
}

// ---------------- CSR pull aggregation, exact two-phase softmax ----------------
// warp per destination node; lanes hold 2 channels each
template <bool SECOND>
__global__ void aggregate(const float* __restrict__ bias) {
    int gt = blockIdx.x * blockDim.x + threadIdx.x;
    int d = gt >> 5;
    int lane = gt & 31;
    if (d >= N_NODES) return;
    int beg = g_rowoff[d], end = g_rowoff[d + 1];
    float sd = g_sdst[d];

    // phase 1: lanes parallel over edges -> exact (max, den)
    float ml = NEG_BIG, dl = 0.0f;
    for (int j = beg + lane; j < end; j += 32) {
        int s = g_csrc[j];
        float e = g_ssrc[s] + sd;
        e = (e > 0.0f) ? e : NEG_SLOPE * e;
        float mn = fmaxf(ml, e);
        dl = dl * __expf(ml - mn) + __expf(e - mn);
        ml = mn;
    }
#pragma unroll
    for (int o = 16; o > 0; o >>= 1) {
        float mo = __shfl_xor_sync(0xffffffffu, ml, o);
        float dn = __shfl_xor_sync(0xffffffffu, dl, o);
        float mn = fmaxf(ml, mo);
        dl = dl * __expf(ml - mn) + dn * __expf(mo - mn);
        ml = mn;
    }
    float m = ml;
    float inv = 1.0f / dl;

    // phase 2: serial over edges, no cross-iteration chain
    float a0 = 0.0f, a1 = 0.0f;
    int s_next = g_csrc[beg];
    float ss_next = g_ssrc[s_next];
    for (int j = beg; j < end; j++) {
        int s = s_next;
        float ss = ss_next;
        if (j + 1 < end) {
            s_next = g_csrc[j + 1];
            ss_next = g_ssrc[s_next];
        }
        float e = ss + sd;
        e = (e > 0.0f) ? e : NEG_SLOPE * e;
        float wgt = __expf(e - m);
        float h0 = g_h[(size_t)s * C + lane];
        float h1 = g_h[(size_t)s * C + lane + 32];
        a0 = fmaf(wgt, h0, a0);
        a1 = fmaf(wgt, h1, a1);
    }
    float* o = (SECOND ? g_out1 : g_out0) + (size_t)d * C;
    o[lane]      = a0 * inv + bias[lane];
    o[lane + 32] = a1 * inv + bias[lane + 32];
}

// ---------------- MLP head: tiled GEMM 64->64 (relu) -> 64->10 (relu) ----------------
// block 256 threads, 64 nodes per block
__global__ void mlp_head2(const float* __restrict__ W0, const float* __restrict__ b0,
                          const float* __restrict__ W1, const float* __restrict__ b1,
                          float* __restrict__ out) {
    __shared__ float Ys[64][C + 1];
    __shared__ float W0s[C * C];
    __shared__ float W1s[C * 10];
    __shared__ float b0s[C], b1s[10];

    int tid = threadIdx.x;
    int tx = tid & 15;
    int ty = tid >> 4;
    int nodeBase = blockIdx.x * 64;

    for (int idx = tid; idx < 64 * C; idx += 256) {
        int r = idx >> 6, k = idx & 63;
        int n = nodeBase + r;
        Ys[r][k] = (n < N_NODES) ? g_out1[(size_t)n * C + k] : 0.0f;
    }
    for (int idx = tid; idx < C * C; idx += 256) W0s[idx] = W0[idx];
    for (int idx = tid; idx < C * 10; idx += 256) W1s[idx] = W1[idx];
    if (tid < C) b0s[tid] = b0[tid];
    if (tid < 10) b1s[tid] = b1[tid];
    __syncthreads();

    float acc[4][4];
#pragma unroll
    for (int i = 0; i < 4; i++) {
        float bb = b0s[tx * 4 + i];
        acc[0][i] = bb; acc[1][i] = bb; acc[2][i] = bb; acc[3][i] = bb;
    }
#pragma unroll 4
    for (int k = 0; k < C; k++) {
        float4 b = *(const float4*)&W0s[k * C + tx * 4];
        float a0 = Ys[ty * 4 + 0][k];
        float a1 = Ys[ty * 4 + 1][k];
        float a2 = Ys[ty * 4 + 2][k];
        float a3 = Ys[ty * 4 + 3][k];
        acc[0][0] = fmaf(a0, b.x, acc[0][0]); acc[0][1] = fmaf(a0, b.y, acc[0][1]);
        acc[0][2] = fmaf(a0, b.z, acc[0][2]); acc[0][3] = fmaf(a0, b.w, acc[0][3]);
        acc[1][0] = fmaf(a1, b.x, acc[1][0]); acc[1][1] = fmaf(a1, b.y, acc[1][1]);
        acc[1][2] = fmaf(a1, b.z, acc[1][2]); acc[1][3] = fmaf(a1, b.w, acc[1][3]);
        acc[2][0] = fmaf(a2, b.x, acc[2][0]); acc[2][1] = fmaf(a2, b.y, acc[2][1]);
        acc[2][2] = fmaf(a2, b.z, acc[2][2]); acc[2][3] = fmaf(a2, b.w, acc[2][3]);
        acc[3][0] = fmaf(a3, b.x, acc[3][0]); acc[3][1] = fmaf(a3, b.y, acc[3][1]);
        acc[3][2] = fmaf(a3, b.z, acc[3][2]); acc[3][3] = fmaf(a3, b.w, acc[3][3]);
    }
    __syncthreads();
#pragma unroll
    for (int mi = 0; mi < 4; mi++) {
        int r = ty * 4 + mi;
        Ys[r][tx * 4 + 0] = fmaxf(acc[mi][0], 0.0f);
        Ys[r][tx * 4 + 1] = fmaxf(acc[mi][1], 0.0f);
        Ys[r][tx * 4 + 2] = fmaxf(acc[mi][2], 0.0f);
        Ys[r][tx * 4 + 3] = fmaxf(acc[mi][3], 0.0f);
    }
    __syncthreads();

    // second stage: 64 nodes x 10 classes = 640 outputs
    for (int idx = tid; idx < 640; idx += 256) {
        int r = idx / 10, c = idx - r * 10;
        int n = nodeBase + r;
        if (n >= N_NODES) continue;
        float a = b1s[c];
#pragma unroll 8
        for (int k = 0; k < C; k++)
            a = fmaf(Ys[r][k], W1s[k * 10 + c], a);
        out[n * 10 + c] = fmaxf(a, 0.0f);
    }
}

// ---------------- launch ----------------

extern "C" void kernel_launch(void* const* d_in, const int* in_sizes, int n_in,
                              void* d_out, int out_size) {
    const float* x     = (const float*)d_in[0];
    const int*   ei    = (const int*)d_in[1];
    const float* g0_W  = (const float*)d_in[2];
    const float* g0_as = (const float*)d_in[3];
    const float* g0_ad = (const float*)d_in[4];
    const float* g0_b  = (const float*)d_in[5];
    const float* g1_W  = (const float*)d_in[6];
    const float* g1_as = (const float*)d_in[7];
    const float* g1_ad = (const float*)d_in[8];
    const float* g1_b  = (const float*)d_in[9];
    const float* l0_W  = (const float*)d_in[10];
    const float* l0_b  = (const float*)d_in[11];
    const float* l1_W  = (const float*)d_in[12];
    const float* l1_b  = (const float*)d_in[13];
    float* out = (float*)d_out;

    const int TB = 256;
    const int eb = (ET + TB - 1) / TB;
    const int nb = (N_NODES + TB - 1) / TB;
    const int ab = (N_NODES * 32 + TB - 1) / TB;
    const int gb = (N_NODES + 63) / 64;              // 782

    const int smem0 = (64 * (F_IN + 1) + F_IN * C) * (int)sizeof(float);  // ~65.8 KB
    const int smem1 = (64 * (C + 1) + C * C) * (int)sizeof(float);        // ~33 KB
    cudaFuncSetAttribute(gemm_att2<F_IN, false>,
                         cudaFuncAttributeMaxDynamicSharedMemorySize, smem0);

    // CSR build (once; shared by both layers)
    zero_counts<<<nb, TB>>>();
    prep_hist<<<eb, TB>>>(ei);
    scan_block<<<NSCAN_BLOCKS, BS_SCAN>>>();
    scan_top<<<1, 128>>>();
    scan_add<<<nb, TB>>>();
    csr_fill<<<eb, TB>>>();

    // ---- GAT layer 0 ----
    gemm_att2<F_IN, false><<<gb, 256, smem0>>>(x, g0_W, g0_as, g0_ad);
    aggregate<false><<<ab, TB>>>(g0_b);

    // ---- GAT layer 1 ----
    gemm_att2<C, true><<<gb, 256, smem1>>>(nullptr, g1_W, g1_as, g1_ad);
    aggregate<true><<<ab, TB>>>(g1_b);

    // ---- MLP head ----
    mlp_head2<<<gb, 256>>>(l0_W, l0_b, l1_W, l1_b, out);
}

// round 5
// speedup vs baseline: 2.0467x; 1.0462x over previous
#include <cuda_runtime.h>
#include <math_constants.h>

#define N_NODES 50000
#define N_EDGES 800000
#define ET (N_EDGES + N_NODES)   // + self loops
#define C 64
#define F_IN 128
#define NEG_SLOPE 0.2f
#define NEG_BIG (-1e30f)

#define GB ((N_NODES + 63) / 64)          // 782 gemm tiles
#define HB ((ET + 255) / 256)             // 3321 hist blocks

// ---------------- scratch (static device globals; no allocation) ----------------
__device__ int   g_src[ET];
__device__ int   g_dst[ET];
__device__ int   g_cnt[N_NODES];
__device__ int   g_fill[N_NODES];
__device__ int   g_rowoff[N_NODES + 1];
__device__ int   g_csrc[ET];                     // CSR: src sorted by dst
__device__ float g_h[(size_t)N_NODES * C];
__device__ float g_out0[(size_t)N_NODES * C];
__device__ float g_out1[(size_t)N_NODES * C];
__device__ float g_ssrc[N_NODES];
__device__ float g_sdst[N_NODES];

// ---------------- K1: prep edges + zero counters ----------------
__global__ void prep_all(const int* __restrict__ ei) {
    int i = blockIdx.x * blockDim.x + threadIdx.x;
    if (i < N_NODES) { g_cnt[i] = 0; g_fill[i] = 0; }
    if (i >= ET) return;
    int s, d;
    if (i < N_EDGES) { s = ei[i]; d = ei[N_EDGES + i]; }
    else             { s = i - N_EDGES; d = s; }
    g_src[i] = s;
    g_dst[i] = d;
}

// ---------------- shared GEMM tile body ----------------
// h = X @ W  (X: [N,K], W: [K,64]); s_src = h.att_src; s_dst = h.att_dst
// 256 threads, tile 64 nodes x 64 channels, 4x4 per thread.
template <int K, bool X_FROM_OUT0>
__device__ __forceinline__ void gemm_body(int tile,
                                          const float* __restrict__ Xext,
                                          const float* __restrict__ W,
                                          const float* __restrict__ av_s,
                                          const float* __restrict__ av_d,
                                          float* sm) {
    float (*Xs)[K + 1] = (float (*)[K + 1])sm;            // 64 x (K+1)
    float* Bsm = sm + 64 * (K + 1);                        // K x 64

    const float* X = X_FROM_OUT0 ? g_out0 : Xext;
    int tid = threadIdx.x;
    int tx = tid & 15;
    int ty = tid >> 4;
    int nodeBase = tile * 64;

    for (int idx = tid; idx < 64 * K; idx += 256) {
        int r = idx / K, k = idx - r * K;
        int n = nodeBase + r;
        Xs[r][k] = (n < N_NODES) ? X[(size_t)n * K + k] : 0.0f;
    }
    for (int idx = tid; idx < K * C; idx += 256)
        Bsm[idx] = W[idx];
    __syncthreads();

    float acc[4][4] = {};
#pragma unroll 2
    for (int k = 0; k < K; k++) {
        float4 b = *(const float4*)&Bsm[k * C + tx * 4];
        float a0 = Xs[ty * 4 + 0][k];
        float a1 = Xs[ty * 4 + 1][k];
        float a2 = Xs[ty * 4 + 2][k];
        float a3 = Xs[ty * 4 + 3][k];
        acc[0][0] = fmaf(a0, b.x, acc[0][0]); acc[0][1] = fmaf(a0, b.y, acc[0][1]);
        acc[0][2] = fmaf(a0, b.z, acc[0][2]); acc[0][3] = fmaf(a0, b.w, acc[0][3]);
        acc[1][0] = fmaf(a1, b.x, acc[1][0]); acc[1][1] = fmaf(a1, b.y, acc[1][1]);
        acc[1][2] = fmaf(a1, b.z, acc[1][2]); acc[1][3] = fmaf(a1, b.w, acc[1][3]);
        acc[2][0] = fmaf(a2, b.x, acc[2][0]); acc[2][1] = fmaf(a2, b.y, acc[2][1]);
        acc[2][2] = fmaf(a2, b.z, acc[2][2]); acc[2][3] = fmaf(a2, b.w, acc[2][3]);
        acc[3][0] = fmaf(a3, b.x, acc[3][0]); acc[3][1] = fmaf(a3, b.y, acc[3][1]);
        acc[3][2] = fmaf(a3, b.z, acc[3][2]); acc[3][3] = fmaf(a3, b.w, acc[3][3]);
    }
    __syncthreads();

    float (*Hs)[C + 1] = (float (*)[C + 1])sm;
#pragma unroll
    for (int mi = 0; mi < 4; mi++) {
        int r = ty * 4 + mi;
        int n = nodeBase + r;
        if (n < N_NODES) {
            float4 v = make_float4(acc[mi][0], acc[mi][1], acc[mi][2], acc[mi][3]);
            *(float4*)&g_h[(size_t)n * C + tx * 4] = v;
        }
        Hs[r][tx * 4 + 0] = acc[mi][0];
        Hs[r][tx * 4 + 1] = acc[mi][1];
        Hs[r][tx * 4 + 2] = acc[mi][2];
        Hs[r][tx * 4 + 3] = acc[mi][3];
    }
    __syncthreads();

    int w = tid >> 5, lane = tid & 31;
    float as0 = av_s[lane], as1 = av_s[lane + 32];
    float ad0 = av_d[lane], ad1 = av_d[lane + 32];
    for (int r = w; r < 64; r += 8) {
        float h0 = Hs[r][lane], h1 = Hs[r][lane + 32];
        float p1 = h0 * as0 + h1 * as1;
        float p2 = h0 * ad0 + h1 * ad1;
#pragma unroll
        for (int o = 16; o > 0; o >>= 1) {
            p1 += __shfl_down_sync(0xffffffffu, p1, o);
            p2 += __shfl_down_sync(0xffffffffu, p2, o);
        }
        int n = nodeBase + r;
        if (lane == 0 && n < N_NODES) { g_ssrc[n] = p1; g_sdst[n] = p2; }
    }
}

// ---------------- K2: gemm0 (blocks < GB)  ||  degree histogram (rest) ----------------
__global__ void fused_gemm0_hist(const float* __restrict__ x,
                                 const float* __restrict__ W,
                                 const float* __restrict__ av_s,
                                 const float* __restrict__ av_d) {
    extern __shared__ float sm[];
    if (blockIdx.x < GB) {
        gemm_body<F_IN, false>(blockIdx.x, x, W, av_s, av_d, sm);
    } else {
        int i = (blockIdx.x - GB) * 256 + threadIdx.x;
        if (i < ET) atomicAdd(&g_cnt[g_dst[i]], 1);
    }
}

// ---------------- K3: single-block full prefix scan over 50K counts ----------------
__global__ void scan_all() {
    __shared__ int wsums[32];
    __shared__ int s_carry;
    int t = threadIdx.x;
    int lane = t & 31, w = t >> 5;
    if (t == 0) { s_carry = 0; g_rowoff[0] = 0; }
    __syncthreads();
    for (int base = 0; base < N_NODES; base += 1024) {
        int i = base + t;
        int v = (i < N_NODES) ? g_cnt[i] : 0;
        int xv = v;
#pragma unroll
        for (int o = 1; o < 32; o <<= 1) {
            int y = __shfl_up_sync(0xffffffffu, xv, o);
            if (lane >= o) xv += y;
        }
        if (lane == 31) wsums[w] = xv;
        __syncthreads();
        if (w == 0) {
            int y = wsums[lane];
#pragma unroll
            for (int o = 1; o < 32; o <<= 1) {
                int z = __shfl_up_sync(0xffffffffu, y, o);
                if (lane >= o) y += z;
            }
            wsums[lane] = y;
        }
        __syncthreads();
        int incl = xv + (w > 0 ? wsums[w - 1] : 0) + s_carry;
        if (i < N_NODES) g_rowoff[i + 1] = incl;
        __syncthreads();
        if (t == 0) s_carry += wsums[31];
        __syncthreads();
    }
}

// ---------------- K4: CSR fill ----------------
__global__ void csr_fill() {
    int i = blockIdx.x * blockDim.x + threadIdx.x;
    if (i >= ET) return;
    int d = g_dst[i];
    int pos = g_rowoff[d] + atomicAdd(&g_fill[d], 1);
    g_csrc[pos] = g_src[i];
}

// ---------------- standalone gemm (layer 1) ----------------
template <int K, bool X_FROM_OUT0>
__global__ void gemm_att2(const float* __restrict__ Xext,
                          const float* __restrict__ W,
                          const float* __restrict__ av_s,
                          const float* __restrict__ av_d) {
    extern __shared__ float sm[];
    gemm_body<K, X_FROM_OUT0>(blockIdx.x, Xext, W, av_s, av_d, sm);
}

// ---------------- CSR pull aggregation, exact softmax ----------------
// warp per destination node; lanes hold 2 channels each.
// Fast path (deg<=32): weights & srcs register-cached, broadcast via shfl.
template <bool SECOND>
__global__ void aggregate(const float* __restrict__ bias) {
    int gt = blockIdx.x * blockDim.x + threadIdx.x;
    int d = gt >> 5;
    int lane = gt & 31;
    if (d >= N_NODES) return;
    int beg = g_rowoff[d], end = g_rowoff[d + 1];
    int deg = end - beg;
    float sd = g_sdst[d];
    float a0 = 0.0f, a1 = 0.0f, inv;

    if (deg <= 32) {
        int s = 0;
        float e = NEG_BIG;
        if (lane < deg) {
            s = g_csrc[beg + lane];
            e = g_ssrc[s] + sd;
            e = (e > 0.0f) ? e : NEG_SLOPE * e;
        }
        // butterfly (max, den)
        float ml = e, dl = (lane < deg) ? 1.0f : 0.0f;
#pragma unroll
        for (int o = 16; o > 0; o >>= 1) {
            float mo = __shfl_xor_sync(0xffffffffu, ml, o);
            float dn = __shfl_xor_sync(0xffffffffu, dl, o);
            float mn = fmaxf(ml, mo);
            dl = dl * __expf(ml - mn) + dn * __expf(mo - mn);
            ml = mn;
        }
        inv = 1.0f / dl;
        float wl = (lane < deg) ? __expf(e - ml) : 0.0f;
        for (int j = 0; j < deg; j++) {
            float wj = __shfl_sync(0xffffffffu, wl, j);
            int   sj = __shfl_sync(0xffffffffu, s,  j);
            a0 = fmaf(wj, g_h[(size_t)sj * C + lane],      a0);
            a1 = fmaf(wj, g_h[(size_t)sj * C + lane + 32], a1);
        }
    } else {
        // generic two-phase path
        float ml = NEG_BIG, dl = 0.0f;
        for (int j = beg + lane; j < end; j += 32) {
            int s = g_csrc[j];
            float e = g_ssrc[s] + sd;
            e = (e > 0.0f) ? e : NEG_SLOPE * e;
            float mn = fmaxf(ml, e);
            dl = dl * __expf(ml - mn) + __expf(e - mn);
            ml = mn;
        }
#pragma unroll
        for (int o = 16; o > 0; o >>= 1) {
            float mo = __shfl_xor_sync(0xffffffffu, ml, o);
            float dn = __shfl_xor_sync(0xffffffffu, dl, o);
            float mn = fmaxf(ml, mo);
            dl = dl * __expf(ml - mn) + dn * __expf(mo - mn);
            ml = mn;
        }
        float m = ml;
        inv = 1.0f / dl;
        int s_next = g_csrc[beg];
        float ss_next = g_ssrc[s_next];
        for (int j = beg; j < end; j++) {
            int s = s_next;
            float ss = ss_next;
            if (j + 1 < end) {
                s_next = g_csrc[j + 1];
                ss_next = g_ssrc[s_next];
            }
            float e = ss + sd;
            e = (e > 0.0f) ? e : NEG_SLOPE * e;
            float wgt = __expf(e - m);
            a0 = fmaf(wgt, g_h[(size_t)s * C + lane],      a0);
            a1 = fmaf(wgt, g_h[(size_t)s * C + lane + 32], a1);
        }
    }
    float* o = (SECOND ? g_out1 : g_out0) + (size_t)d * C;
    o[lane]      = a0 * inv + bias[lane];
    o[lane + 32] = a1 * inv + bias[lane + 32];
}

// ---------------- MLP head: tiled GEMM 64->64 (relu) -> 64->10 (relu) ----------------
__global__ void mlp_head2(const float* __restrict__ W0, const float* __restrict__ b0,
                          const float* __restrict__ W1, const float* __restrict__ b1,
                          float* __restrict__ out) {
    __shared__ float Ys[64][C + 1];
    __shared__ float W0s[C * C];
    __shared__ float W1s[C * 10];
    __shared__ float b0s[C], b1s[10];

    int tid = threadIdx.x;
    int tx = tid & 15;
    int ty = tid >> 4;
    int nodeBase = blockIdx.x * 64;

    for (int idx = tid; idx < 64 * C; idx += 256) {
        int r = idx >> 6, k = idx & 63;
        int n = nodeBase + r;
        Ys[r][k] = (n < N_NODES) ? g_out1[(size_t)n * C + k] : 0.0f;
    }
    for (int idx = tid; idx < C * C; idx += 256) W0s[idx] = W0[idx];
    for (int idx = tid; idx < C * 10; idx += 256) W1s[idx] = W1[idx];
    if (tid < C) b0s[tid] = b0[tid];
    if (tid < 10) b1s[tid] = b1[tid];
    __syncthreads();

    float acc[4][4];
#pragma unroll
    for (int i = 0; i < 4; i++) {
        float bb = b0s[tx * 4 + i];
        acc[0][i] = bb; acc[1][i] = bb; acc[2][i] = bb; acc[3][i] = bb;
    }
#pragma unroll 4
    for (int k = 0; k < C; k++) {
        float4 b = *(const float4*)&W0s[k * C + tx * 4];
        float a0 = Ys[ty * 4 + 0][k];
        float a1 = Ys[ty * 4 + 1][k];
        float a2 = Ys[ty * 4 + 2][k];
        float a3 = Ys[ty * 4 + 3][k];
        acc[0][0] = fmaf(a0, b.x, acc[0][0]); acc[0][1] = fmaf(a0, b.y, acc[0][1]);
        acc[0][2] = fmaf(a0, b.z, acc[0][2]); acc[0][3] = fmaf(a0, b.w, acc[0][3]);
        acc[1][0] = fmaf(a1, b.x, acc[1][0]); acc[1][1] = fmaf(a1, b.y, acc[1][1]);
        acc[1][2] = fmaf(a1, b.z, acc[1][2]); acc[1][3] = fmaf(a1, b.w, acc[1][3]);
        acc[2][0] = fmaf(a2, b.x, acc[2][0]); acc[2][1] = fmaf(a2, b.y, acc[2][1]);
        acc[2][2] = fmaf(a2, b.z, acc[2][2]); acc[2][3] = fmaf(a2, b.w, acc[2][3]);
        acc[3][0] = fmaf(a3, b.x, acc[3][0]); acc[3][1] = fmaf(a3, b.y, acc[3][1]);
        acc[3][2] = fmaf(a3, b.z, acc[3][2]); acc[3][3] = fmaf(a3, b.w, acc[3][3]);
    }
    __syncthreads();
#pragma unroll
    for (int mi = 0; mi < 4; mi++) {
        int r = ty * 4 + mi;
        Ys[r][tx * 4 + 0] = fmaxf(acc[mi][0], 0.0f);
        Ys[r][tx * 4 + 1] = fmaxf(acc[mi][1], 0.0f);
        Ys[r][tx * 4 + 2] = fmaxf(acc[mi][2], 0.0f);
        Ys[r][tx * 4 + 3] = fmaxf(acc[mi][3], 0.0f);
    }
    __syncthreads();

    for (int idx = tid; idx < 640; idx += 256) {
        int r = idx / 10, c = idx - r * 10;
        int n = nodeBase + r;
        if (n >= N_NODES) continue;
        float a = b1s[c];
#pragma unroll 8
        for (int k = 0; k < C; k++)
            a = fmaf(Ys[r][k], W1s[k * 10 + c], a);
        out[n * 10 + c] = fmaxf(a, 0.0f);
    }
}

// ---------------- launch ----------------

extern "C" void kernel_launch(void* const* d_in, const int* in_sizes, int n_in,
                              void* d_out, int out_size) {
    const float* x     = (const float*)d_in[0];
    const int*   ei    = (const int*)d_in[1];
    const float* g0_W  = (const float*)d_in[2];
    const float* g0_as = (const float*)d_in[3];
    const float* g0_ad = (const float*)d_in[4];
    const float* g0_b  = (const float*)d_in[5];
    const float* g1_W  = (const float*)d_in[6];
    const float* g1_as = (const float*)d_in[7];
    const float* g1_ad = (const float*)d_in[8];
    const float* g1_b  = (const float*)d_in[9];
    const float* l0_W  = (const float*)d_in[10];
    const float* l0_b  = (const float*)d_in[11];
    const float* l1_W  = (const float*)d_in[12];
    const float* l1_b  = (const float*)d_in[13];
    float* out = (float*)d_out;

    const int TB = 256;
    const int eb = (ET + TB - 1) / TB;
    const int ab = (N_NODES * 32 + TB - 1) / TB;

    const int smem0 = (64 * (F_IN + 1) + F_IN * C) * (int)sizeof(float);  // ~65.8 KB
    const int smem1 = (64 * (C + 1) + C * C) * (int)sizeof(float);        // ~33 KB
    cudaFuncSetAttribute(fused_gemm0_hist,
                         cudaFuncAttributeMaxDynamicSharedMemorySize, smem0);

    // K1: edge prep + zero counters
    prep_all<<<eb, TB>>>(ei);
    // K2: gemm layer-0 || degree histogram
    fused_gemm0_hist<<<GB + HB, TB, smem0>>>(x, g0_W, g0_as, g0_ad);
    // K3: full prefix scan (single block)
    scan_all<<<1, 1024>>>();
    // K4: CSR fill
    csr_fill<<<eb, TB>>>();
    // K5: aggregate layer 0
    aggregate<false><<<ab, TB>>>(g0_b);
    // K6: gemm layer 1
    gemm_att2<C, true><<<GB, TB, smem1>>>(nullptr, g1_W, g1_as, g1_ad);
    // K7: aggregate layer 1
    aggregate<true><<<ab, TB>>>(g1_b);
    // K8: MLP head
    mlp_head2<<<GB, TB>>>(l0_W, l0_b, l1_W, l1_b, out);
}